// round 3
// baseline (speedup 1.0000x reference)
#include <cuda_runtime.h>
#include <cstdint>

// Chamfer distance, B=4, N=4096, D=3.
// final = sum over {2 dirs x 4 batches x 4096 points} of sqrt(min_j d2) / (2*N*B)
//
// Main kernel: grid (4 a-chunks, 4 batches, 8 = dir*4 + jslice), 256 threads.
// Each block: loads a 1024-point slice of the "other" cloud into shared
// (coords + |b|^2, packed as float2 pairs), each thread owns 4 a-points and
// scans the slice with packed f32x2 FMAs:
//   d2(pair) = fma(-2az, bz, fma(-2ay, by, fma(-2ax, bx, |a|^2 + |b|^2)))
// Partial mins combined across j-slices via atomicMin on float-as-uint
// (all distances >= 0, so uint order == float order). Deterministic.

#define NB 4
#define NP 4096
#define NSLOTS (2 * NB * NP) /* 32768 */

__device__ unsigned int g_min[NSLOTS];

__device__ __forceinline__ unsigned long long pack2(float lo, float hi) {
    unsigned long long r;
    asm("mov.b64 %0, {%1, %2};" : "=l"(r) : "f"(lo), "f"(hi));
    return r;
}
__device__ __forceinline__ void unpack2(unsigned long long v, float& lo, float& hi) {
    asm("mov.b64 {%0, %1}, %2;" : "=f"(lo), "=f"(hi) : "l"(v));
}
__device__ __forceinline__ unsigned long long addx2(unsigned long long a, unsigned long long b) {
    unsigned long long r;
    asm("add.rn.f32x2 %0, %1, %2;" : "=l"(r) : "l"(a), "l"(b));
    return r;
}
__device__ __forceinline__ unsigned long long fmafx2(unsigned long long a, unsigned long long b,
                                                     unsigned long long c) {
    unsigned long long r;
    asm("fma.rn.f32x2 %0, %1, %2, %3;" : "=l"(r) : "l"(a), "l"(b), "l"(c));
    return r;
}

__global__ void init_kernel() {
    int i = blockIdx.x * blockDim.x + threadIdx.x;
    if (i < NSLOTS) g_min[i] = 0x7F800000u;  // +inf
}

__global__ __launch_bounds__(256) void chamfer_main(const float* __restrict__ pc1,
                                                    const float* __restrict__ pc2) {
    // 1024 b-points per slice, stored as 512 float2 pairs per component.
    __shared__ float2 sx[512], sy[512], sz[512], sw[512];

    const int tid = threadIdx.x;
    const int achunk = blockIdx.x;      // 0..3  (1024 a-points each)
    const int batch = blockIdx.y;       // 0..3
    const int dir = blockIdx.z >> 2;    // 0: pc1->pc2, 1: pc2->pc1
    const int slice = blockIdx.z & 3;   // 0..3  (1024 b-points each)

    const float* Abase = (dir ? pc2 : pc1) + (size_t)batch * NP * 3;
    const float* Bbase = (dir ? pc1 : pc2) + (size_t)batch * NP * 3 + (size_t)slice * 1024 * 3;

    // Load b-slice: coords + squared norm, as packed pairs.
    for (int j = tid; j < 1024; j += 256) {
        float bx = Bbase[j * 3 + 0];
        float by = Bbase[j * 3 + 1];
        float bz = Bbase[j * 3 + 2];
        ((float*)sx)[j] = bx;
        ((float*)sy)[j] = by;
        ((float*)sz)[j] = bz;
        ((float*)sw)[j] = bx * bx + by * by + bz * bz;
    }
    __syncthreads();

    // Each thread owns 4 a-points (strided by 256 within the 1024-point chunk).
    unsigned long long nax[4], nay[4], naz[4], asq[4];
    float mlo[4], mhi[4];
#pragma unroll
    for (int k = 0; k < 4; ++k) {
        int p = achunk * 1024 + k * 256 + tid;
        float ax = Abase[p * 3 + 0];
        float ay = Abase[p * 3 + 1];
        float az = Abase[p * 3 + 2];
        float nx = -2.0f * ax, ny = -2.0f * ay, nz = -2.0f * az;
        float aq = ax * ax + ay * ay + az * az;
        nax[k] = pack2(nx, nx);
        nay[k] = pack2(ny, ny);
        naz[k] = pack2(nz, nz);
        asq[k] = pack2(aq, aq);
        mlo[k] = 3.4e38f;
        mhi[k] = 3.4e38f;
    }

#pragma unroll 4
    for (int j = 0; j < 512; ++j) {
        float2 vx = sx[j], vy = sy[j], vz = sz[j], vw = sw[j];
        unsigned long long bx = pack2(vx.x, vx.y);
        unsigned long long by = pack2(vy.x, vy.y);
        unsigned long long bz = pack2(vz.x, vz.y);
        unsigned long long bw = pack2(vw.x, vw.y);
#pragma unroll
        for (int k = 0; k < 4; ++k) {
            unsigned long long t = addx2(asq[k], bw);        // |a|^2 + |b|^2
            t = fmafx2(nax[k], bx, t);
            t = fmafx2(nay[k], by, t);
            t = fmafx2(naz[k], bz, t);
            float lo, hi;
            unpack2(t, lo, hi);
            mlo[k] = fminf(mlo[k], lo);
            mhi[k] = fminf(mhi[k], hi);
        }
    }

#pragma unroll
    for (int k = 0; k < 4; ++k) {
        float m = fminf(mlo[k], mhi[k]);
        m = fmaxf(m, 0.0f);  // expansion can dip slightly negative
        int p = achunk * 1024 + k * 256 + tid;
        atomicMin(&g_min[dir * (NB * NP) + batch * NP + p], __float_as_uint(m));
    }
}

__global__ __launch_bounds__(1024) void finalize_kernel(float* out) {
    __shared__ float red[1024];
    int tid = threadIdx.x;
    float s = 0.0f;
    for (int i = tid; i < NSLOTS; i += 1024)
        s += sqrtf(__uint_as_float(g_min[i]));
    red[tid] = s;
    __syncthreads();
    for (int off = 512; off > 0; off >>= 1) {
        if (tid < off) red[tid] += red[tid + off];
        __syncthreads();
    }
    if (tid == 0) out[0] = red[0] * (1.0f / (float)NSLOTS);
}

extern "C" void kernel_launch(void* const* d_in, const int* in_sizes, int n_in,
                              void* d_out, int out_size) {
    const float* pc1 = (const float*)d_in[0];
    const float* pc2 = (const float*)d_in[1];

    init_kernel<<<(NSLOTS + 255) / 256, 256>>>();
    chamfer_main<<<dim3(4, 4, 8), 256>>>(pc1, pc2);
    finalize_kernel<<<1, 1024>>>((float*)d_out);
}